// round 1
// baseline (speedup 1.0000x reference)
#include <cuda_runtime.h>
#include <cstdint>

// Flag: 1 if the index tensor is int64, 0 if int32.
__device__ int g_idx_is_i64;

// Single-thread detection: for int64 little-endian non-negative indices,
// every odd 32-bit word is 0. For int32 indices in [0,128000), the odds that
// 32 random words are all zero are ~(1/128000)^32 ~= 0.
__global__ void detect_idx_dtype_kernel(const unsigned int* __restrict__ xw,
                                        int n_words_to_check) {
    bool all_zero = true;
    for (int i = 1; i < n_words_to_check; i += 2) {
        if (xw[i] != 0u) { all_zero = false; break; }
    }
    g_idx_is_i64 = all_zero ? 1 : 0;
}

// One float4 (4 output elements) per thread.
//  gid >> log2(chunks_per_row) = token, low bits = 16B chunk within the row.
// Row reads are 128 consecutive threads * 16B = fully coalesced 2KB bursts.
__global__ __launch_bounds__(256)
void quant_embed_kernel(const void* __restrict__ x_raw,
                        const int4* __restrict__ w4,     // weight_q as int4
                        const float* __restrict__ scales,
                        float4* __restrict__ out4,
                        int chunks_per_row,              // dim/4 = 128
                        int log2_chunks,                 // 7
                        long long n4)                    // total float4s
{
    long long gid = (long long)blockIdx.x * blockDim.x + threadIdx.x;
    if (gid >= n4) return;

    long long token = gid >> log2_chunks;
    int col = (int)(gid & (chunks_per_row - 1));

    long long idx;
    if (g_idx_is_i64) {
        idx = ((const long long*)x_raw)[token];
    } else {
        idx = (long long)((const int*)x_raw)[token];
    }

    float s = __ldg(&scales[idx]);
    int4 w = __ldg(&w4[idx * chunks_per_row + col]);

    float4 o;
    o.x = (float)w.x * s;
    o.y = (float)w.y * s;
    o.z = (float)w.z * s;
    o.w = (float)w.w * s;
    out4[gid] = o;
}

extern "C" void kernel_launch(void* const* d_in, const int* in_sizes, int n_in,
                              void* d_out, int out_size) {
    // Inputs per reference: x [batch*seq] (int64 or int32), weight_q [vocab, dim] int32,
    // scales [vocab] float32. Output float32 [batch, seq, dim].
    const void*  x       = d_in[0];
    const int4*  w4      = (const int4*)d_in[1];
    const float* scales  = (const float*)d_in[2];
    float4*      out4    = (float4*)d_out;

    const int n_tokens = in_sizes[0];
    const int dim      = out_size / n_tokens;          // 512
    const int chunks   = dim / 4;                      // 128 float4 per row
    int log2_chunks = 0;
    while ((1 << log2_chunks) < chunks) log2_chunks++; // 7

    // Dtype detection (cheap single-thread kernel, runs every call -> deterministic,
    // graph-capturable).
    int words_to_check = 64;
    if (n_tokens < 32) words_to_check = n_tokens * 2;
    detect_idx_dtype_kernel<<<1, 1>>>((const unsigned int*)x, words_to_check);

    const long long n4 = (long long)n_tokens * chunks;
    const int threads = 256;
    const int blocks = (int)((n4 + threads - 1) / threads);

    quant_embed_kernel<<<blocks, threads>>>(x, w4, scales, out4,
                                            chunks, log2_chunks, n4);
}

// round 2
// speedup vs baseline: 1.1005x; 1.1005x over previous
#include <cuda_runtime.h>
#include <cstdint>

// Flag: 1 if the index tensor is int64, 0 if int32.
__device__ int g_idx_is_i64;

// Single-thread detection: for int64 little-endian non-negative indices,
// every odd 32-bit word is 0. For int32 indices in [0,128000) the odds that
// 32 random odd words are all zero are astronomically small.
__global__ void detect_idx_dtype_kernel(const unsigned int* __restrict__ xw,
                                        int n_words_to_check) {
    bool all_zero = true;
    for (int i = 1; i < n_words_to_check; i += 2) {
        if (xw[i] != 0u) { all_zero = false; break; }
    }
    g_idx_is_i64 = all_zero ? 1 : 0;
}

// One WARP per token. Lane l handles int4 chunks l, l+32, l+64, l+96 of the
// 2KB row: 4 independent 16B loads issued back-to-back -> MLP>=4 on the
// DRAM-critical gather, vs 1 in the previous kernel. idx/scale are single
// broadcast loads per warp instead of per-thread.
__global__ __launch_bounds__(256)
void quant_embed_warp_kernel(const void* __restrict__ x_raw,
                             const int4* __restrict__ w4,   // weight table as int4
                             const float* __restrict__ scales,
                             float4* __restrict__ out4,
                             int chunks_per_row,            // dim/4 (=128)
                             int n_tokens)
{
    const int warps_per_block = blockDim.x >> 5;
    const int warp_id = threadIdx.x >> 5;
    const int lane    = threadIdx.x & 31;
    const int token   = blockIdx.x * warps_per_block + warp_id;
    if (token >= n_tokens) return;

    long long idx;
    if (g_idx_is_i64) {
        idx = ((const long long*)x_raw)[token];
    } else {
        idx = (long long)((const int*)x_raw)[token];
    }

    const int4*  wrow = w4 + idx * chunks_per_row;
    float4*      orow = out4 + (long long)token * chunks_per_row;

    const int per_lane = chunks_per_row >> 5;   // 4 for dim=512

    if (per_lane == 4) {
        // Issue all independent loads before any consume.
        int4 w0 = __ldg(&wrow[lane]);
        int4 w1 = __ldg(&wrow[lane + 32]);
        int4 w2 = __ldg(&wrow[lane + 64]);
        int4 w3 = __ldg(&wrow[lane + 96]);
        float s = __ldg(&scales[idx]);

        float4 o0 = make_float4((float)w0.x * s, (float)w0.y * s,
                                (float)w0.z * s, (float)w0.w * s);
        float4 o1 = make_float4((float)w1.x * s, (float)w1.y * s,
                                (float)w1.z * s, (float)w1.w * s);
        float4 o2 = make_float4((float)w2.x * s, (float)w2.y * s,
                                (float)w2.z * s, (float)w2.w * s);
        float4 o3 = make_float4((float)w3.x * s, (float)w3.y * s,
                                (float)w3.z * s, (float)w3.w * s);

        orow[lane]      = o0;
        orow[lane + 32] = o1;
        orow[lane + 64] = o2;
        orow[lane + 96] = o3;
    } else {
        // Generic fallback for other dims.
        float s = __ldg(&scales[idx]);
        for (int c = lane; c < chunks_per_row; c += 32) {
            int4 w = __ldg(&wrow[c]);
            orow[c] = make_float4((float)w.x * s, (float)w.y * s,
                                  (float)w.z * s, (float)w.w * s);
        }
    }
}

extern "C" void kernel_launch(void* const* d_in, const int* in_sizes, int n_in,
                              void* d_out, int out_size) {
    // Inputs: x [batch*seq] (int64 or int32), weight_q [vocab, dim] int32,
    // scales [vocab] float32. Output float32 [batch*seq, dim].
    const void*  x      = d_in[0];
    const int4*  w4     = (const int4*)d_in[1];
    const float* scales = (const float*)d_in[2];
    float4*      out4   = (float4*)d_out;

    const int n_tokens = in_sizes[0];
    const int dim      = out_size / n_tokens;   // 512
    const int chunks   = dim / 4;               // 128

    int words_to_check = 64;
    if (n_tokens < 32) words_to_check = n_tokens * 2;
    detect_idx_dtype_kernel<<<1, 1>>>((const unsigned int*)x, words_to_check);

    const int threads = 256;
    const int warps_per_block = threads / 32;   // 8 tokens per block
    const int blocks = (n_tokens + warps_per_block - 1) / warps_per_block;

    quant_embed_warp_kernel<<<blocks, threads>>>(x, w4, scales, out4,
                                                 chunks, n_tokens);
}

// round 3
// speedup vs baseline: 1.1059x; 1.0049x over previous
#include <cuda_runtime.h>
#include <cstdint>

// Flag: 1 if the index tensor is int64, 0 if int32.
__device__ int g_idx_is_i64;

// Single-thread detection: for int64 little-endian non-negative indices,
// every odd 32-bit word is 0. For int32 indices in [0,128000) the odds that
// 32 random odd words are all zero are astronomically small.
__global__ void detect_idx_dtype_kernel(const unsigned int* __restrict__ xw,
                                        int n_words_to_check) {
    bool all_zero = true;
    for (int i = 1; i < n_words_to_check; i += 2) {
        if (xw[i] != 0u) { all_zero = false; break; }
    }
    g_idx_is_i64 = all_zero ? 1 : 0;
}

#define WARPS_PER_BLOCK 8
#define TOK_PER_WARP    2
#define CHUNKS          128   // dim 512 / 4 = int4 chunks per row

__device__ __forceinline__ unsigned smem_u32(const void* p) {
    return (unsigned)__cvta_generic_to_shared(p);
}

__device__ __forceinline__ void cp_async16(unsigned dst, const void* src) {
    asm volatile("cp.async.cg.shared.global [%0], [%1], 16;\n"
                 :: "r"(dst), "l"(src) : "memory");
}
__device__ __forceinline__ void cp_commit() {
    asm volatile("cp.async.commit_group;\n" ::: "memory");
}
template <int N>
__device__ __forceinline__ void cp_wait() {
    asm volatile("cp.async.wait_group %0;\n" :: "n"(N) : "memory");
}

// One warp per TOK_PER_WARP tokens. Rows are staged through shared memory via
// cp.async (LDGSTS): no register pressure, no outstanding-depth cap, so each
// warp keeps 2 full rows (4KB) in flight while dequantizing the first.
// Each lane reads back only the 16B chunks it copied -> per-thread
// wait_group ordering suffices, zero barriers.
__global__ __launch_bounds__(WARPS_PER_BLOCK * 32)
void quant_embed_cpasync_kernel(const void* __restrict__ x_raw,
                                const int4* __restrict__ w4,
                                const float* __restrict__ scales,
                                float4* __restrict__ out4,
                                int n_tokens)
{
    __shared__ __align__(16) int4 stage[WARPS_PER_BLOCK * TOK_PER_WARP * CHUNKS];

    const int warp_id = threadIdx.x >> 5;
    const int lane    = threadIdx.x & 31;
    const int base_token = (blockIdx.x * WARPS_PER_BLOCK + warp_id) * TOK_PER_WARP;
    if (base_token >= n_tokens) return;

    const bool is64 = (g_idx_is_i64 != 0);

    // Lanes 0..TOK_PER_WARP-1 load the indices; broadcast via shuffle.
    long long myidx = 0;
    if (lane < TOK_PER_WARP && base_token + lane < n_tokens) {
        myidx = is64 ? ((const long long*)x_raw)[base_token + lane]
                     : (long long)((const int*)x_raw)[base_token + lane];
    }
    long long idx0 = __shfl_sync(0xFFFFFFFFu, myidx, 0);
    long long idx1 = __shfl_sync(0xFFFFFFFFu, myidx, 1);

    int4* ws = stage + (warp_id * TOK_PER_WARP) * CHUNKS;

    // Issue token 0's row (4 x warp-wide 16B cp.async = 2KB), commit.
    {
        const int4* src = w4 + idx0 * CHUNKS;
        #pragma unroll
        for (int c = 0; c < 4; c++)
            cp_async16(smem_u32(ws + c * 32 + lane), src + c * 32 + lane);
        cp_commit();
    }
    // Token 1's row, commit.
    const bool has1 = (base_token + 1) < n_tokens;
    if (has1) {
        const int4* src = w4 + idx1 * CHUNKS;
        #pragma unroll
        for (int c = 0; c < 4; c++)
            cp_async16(smem_u32(ws + CHUNKS + c * 32 + lane), src + c * 32 + lane);
    }
    cp_commit();

    // Scales overlap with the in-flight copies (scales table is L2-resident).
    float s0 = __ldg(&scales[idx0]);
    float s1 = has1 ? __ldg(&scales[idx1]) : 0.0f;

    // Process token 0 while token 1 is still in flight.
    cp_wait<1>();
    {
        float4* orow = out4 + (long long)base_token * CHUNKS;
        #pragma unroll
        for (int c = 0; c < 4; c++) {
            int4 w = ws[c * 32 + lane];
            orow[c * 32 + lane] = make_float4((float)w.x * s0, (float)w.y * s0,
                                              (float)w.z * s0, (float)w.w * s0);
        }
    }

    cp_wait<0>();
    if (has1) {
        float4* orow = out4 + (long long)(base_token + 1) * CHUNKS;
        #pragma unroll
        for (int c = 0; c < 4; c++) {
            int4 w = ws[CHUNKS + c * 32 + lane];
            orow[c * 32 + lane] = make_float4((float)w.x * s1, (float)w.y * s1,
                                              (float)w.z * s1, (float)w.w * s1);
        }
    }
}

// Generic fallback for dims other than 512 (kept for safety; reference uses 512).
__global__ __launch_bounds__(256)
void quant_embed_generic_kernel(const void* __restrict__ x_raw,
                                const int4* __restrict__ w4,
                                const float* __restrict__ scales,
                                float4* __restrict__ out4,
                                int chunks_per_row, int n_tokens)
{
    const int warps_per_block = blockDim.x >> 5;
    const int token = blockIdx.x * warps_per_block + (threadIdx.x >> 5);
    const int lane  = threadIdx.x & 31;
    if (token >= n_tokens) return;
    long long idx = g_idx_is_i64 ? ((const long long*)x_raw)[token]
                                 : (long long)((const int*)x_raw)[token];
    float s = __ldg(&scales[idx]);
    const int4* wrow = w4 + idx * chunks_per_row;
    float4* orow = out4 + (long long)token * chunks_per_row;
    for (int c = lane; c < chunks_per_row; c += 32) {
        int4 w = __ldg(&wrow[c]);
        orow[c] = make_float4((float)w.x * s, (float)w.y * s,
                              (float)w.z * s, (float)w.w * s);
    }
}

extern "C" void kernel_launch(void* const* d_in, const int* in_sizes, int n_in,
                              void* d_out, int out_size) {
    const void*  x      = d_in[0];
    const int4*  w4     = (const int4*)d_in[1];
    const float* scales = (const float*)d_in[2];
    float4*      out4   = (float4*)d_out;

    const int n_tokens = in_sizes[0];
    const int dim      = out_size / n_tokens;   // 512
    const int chunks   = dim / 4;               // 128

    int words_to_check = 64;
    if (n_tokens < 32) words_to_check = n_tokens * 2;
    detect_idx_dtype_kernel<<<1, 1>>>((const unsigned int*)x, words_to_check);

    if (chunks == CHUNKS) {
        const int tokens_per_block = WARPS_PER_BLOCK * TOK_PER_WARP;  // 16
        const int blocks = (n_tokens + tokens_per_block - 1) / tokens_per_block;
        quant_embed_cpasync_kernel<<<blocks, WARPS_PER_BLOCK * 32>>>(
            x, w4, scales, out4, n_tokens);
    } else {
        const int threads = 256;
        const int wpb = threads / 32;
        const int blocks = (n_tokens + wpb - 1) / wpb;
        quant_embed_generic_kernel<<<blocks, threads>>>(x, w4, scales, out4,
                                                        chunks, n_tokens);
    }
}

// round 4
// speedup vs baseline: 1.1310x; 1.0227x over previous
#include <cuda_runtime.h>
#include <cstdint>

#define WARPS_PER_BLOCK 8
#define TOK_PER_WARP    4
#define CHUNKS          128   // dim 512 / 4 int4 chunks per row (2KB row)

__device__ __forceinline__ unsigned smem_u32(const void* p) {
    return (unsigned)__cvta_generic_to_shared(p);
}
__device__ __forceinline__ void cp_async16(unsigned dst, const void* src) {
    asm volatile("cp.async.cg.shared.global [%0], [%1], 16;\n"
                 :: "r"(dst), "l"(src) : "memory");
}
__device__ __forceinline__ void cp_commit() {
    asm volatile("cp.async.commit_group;\n" ::: "memory");
}
template <int N>
__device__ __forceinline__ void cp_wait() {
    asm volatile("cp.async.wait_group %0;\n" :: "n"(N) : "memory");
}

// One warp handles TOK_PER_WARP tokens with a depth-2 cp.async pipeline.
// Index dtype (int64 vs int32) detected inline: for little-endian non-negative
// int64 indices every odd 32-bit word is 0; 32 words all zero for random int32
// in [0,128000) has probability (1/128000)^32 ~= 0.
__global__ __launch_bounds__(WARPS_PER_BLOCK * 32)
void quant_embed_pipe_kernel(const unsigned int* __restrict__ x_raw,
                             const int4* __restrict__ w4,
                             const float* __restrict__ scales,
                             float4* __restrict__ out4,
                             int n_tokens)
{
    // 2 buffers x 2KB per warp
    __shared__ __align__(16) int4 stage[WARPS_PER_BLOCK * 2 * CHUNKS];

    const int warp_id = threadIdx.x >> 5;
    const int lane    = threadIdx.x & 31;

    // ---- inline dtype detection (uniform across grid; no extra kernel) ----
    // lane l inspects odd word 2l+1 (guarded for tiny n_tokens).
    unsigned probe = 0u;
    {
        int wmax = n_tokens * 2;        // words available if int64; >= n_tokens if int32
        int widx = 2 * lane + 1;
        if (widx < wmax) probe = x_raw[widx];
    }
    const bool is64 = (__ballot_sync(0xFFFFFFFFu, probe != 0u) == 0u);

    const int base_token = (blockIdx.x * WARPS_PER_BLOCK + warp_id) * TOK_PER_WARP;
    if (base_token >= n_tokens) return;

    // ---- load all indices + scales for this warp up front ----
    long long myidx = 0;
    if (lane < TOK_PER_WARP && base_token + lane < n_tokens) {
        myidx = is64 ? (long long)((const long long*)x_raw)[base_token + lane]
                     : (long long)((const int*)x_raw)[base_token + lane];
    }
    long long idx[TOK_PER_WARP];
    #pragma unroll
    for (int t = 0; t < TOK_PER_WARP; t++)
        idx[t] = __shfl_sync(0xFFFFFFFFu, myidx, t);

    float mys = (lane < TOK_PER_WARP && base_token + lane < n_tokens)
                    ? __ldg(&scales[myidx]) : 0.0f;
    float sc[TOK_PER_WARP];
    #pragma unroll
    for (int t = 0; t < TOK_PER_WARP; t++)
        sc[t] = __shfl_sync(0xFFFFFFFFu, mys, t);

    int4* buf0 = stage + warp_id * 2 * CHUNKS;
    int4* buf1 = buf0 + CHUNKS;

    const int n_here = min(TOK_PER_WARP, n_tokens - base_token);

    // ---- prologue: fill both buffers ----
    {
        const int4* src = w4 + idx[0] * CHUNKS;
        #pragma unroll
        for (int c = 0; c < 4; c++)
            cp_async16(smem_u32(buf0 + c * 32 + lane), src + c * 32 + lane);
        cp_commit();
    }
    if (n_here > 1) {
        const int4* src = w4 + idx[1] * CHUNKS;
        #pragma unroll
        for (int c = 0; c < 4; c++)
            cp_async16(smem_u32(buf1 + c * 32 + lane), src + c * 32 + lane);
    }
    cp_commit();

    // ---- steady state ----
    #pragma unroll
    for (int t = 0; t < TOK_PER_WARP; t++) {
        if (t >= n_here) break;
        cp_wait<1>();                      // oldest group complete
        int4* buf = (t & 1) ? buf1 : buf0;
        const float s = sc[t];
        float4* orow = out4 + (long long)(base_token + t) * CHUNKS;
        #pragma unroll
        for (int c = 0; c < 4; c++) {
            int4 w = buf[c * 32 + lane];
            float4 o = make_float4((float)w.x * s, (float)w.y * s,
                                   (float)w.z * s, (float)w.w * s);
            __stcs(&orow[c * 32 + lane], o);   // streaming store: don't pollute L2
        }
        // refill this buffer with token t+2
        if (t + 2 < n_here) {
            const int4* src = w4 + idx[t + 2] * CHUNKS;
            #pragma unroll
            for (int c = 0; c < 4; c++)
                cp_async16(smem_u32(buf + c * 32 + lane), src + c * 32 + lane);
        }
        cp_commit();   // keep group count consistent every iteration
    }
    cp_wait<0>();
}

// Generic fallback for dims other than 512.
__global__ __launch_bounds__(256)
void quant_embed_generic_kernel(const unsigned int* __restrict__ x_raw,
                                const int4* __restrict__ w4,
                                const float* __restrict__ scales,
                                float4* __restrict__ out4,
                                int chunks_per_row, int n_tokens)
{
    const int lane = threadIdx.x & 31;
    unsigned probe = 0u;
    {
        int wmax = n_tokens * 2;
        int widx = 2 * lane + 1;
        if (widx < wmax) probe = x_raw[widx];
    }
    const bool is64 = (__ballot_sync(0xFFFFFFFFu, probe != 0u) == 0u);

    const int warps_per_block = blockDim.x >> 5;
    const int token = blockIdx.x * warps_per_block + (threadIdx.x >> 5);
    if (token >= n_tokens) return;
    long long idx = is64 ? ((const long long*)x_raw)[token]
                         : (long long)((const int*)x_raw)[token];
    float s = __ldg(&scales[idx]);
    const int4* wrow = w4 + idx * chunks_per_row;
    float4* orow = out4 + (long long)token * chunks_per_row;
    for (int c = lane; c < chunks_per_row; c += 32) {
        int4 w = __ldg(&wrow[c]);
        orow[c] = make_float4((float)w.x * s, (float)w.y * s,
                              (float)w.z * s, (float)w.w * s);
    }
}

extern "C" void kernel_launch(void* const* d_in, const int* in_sizes, int n_in,
                              void* d_out, int out_size) {
    const unsigned int* x      = (const unsigned int*)d_in[0];
    const int4*         w4     = (const int4*)d_in[1];
    const float*        scales = (const float*)d_in[2];
    float4*             out4   = (float4*)d_out;

    const int n_tokens = in_sizes[0];
    const int dim      = out_size / n_tokens;   // 512
    const int chunks   = dim / 4;               // 128

    if (chunks == CHUNKS) {
        const int tokens_per_block = WARPS_PER_BLOCK * TOK_PER_WARP;  // 32
        const int blocks = (n_tokens + tokens_per_block - 1) / tokens_per_block;
        quant_embed_pipe_kernel<<<blocks, WARPS_PER_BLOCK * 32>>>(
            x, w4, scales, out4, n_tokens);
    } else {
        const int threads = 256;
        const int wpb = threads / 32;
        const int blocks = (n_tokens + wpb - 1) / wpb;
        quant_embed_generic_kernel<<<blocks, threads>>>(x, w4, scales, out4,
                                                        chunks, n_tokens);
    }
}

// round 5
// speedup vs baseline: 1.3129x; 1.1608x over previous
#include <cuda_runtime.h>
#include <cstdint>

#define WARPS_PER_BLOCK 8
#define TOK_PER_WARP    2
#define CHUNKS          128   // dim 512 / 4 int4 chunks per row (2KB row)

// 16B non-coherent load with 256B L2 fetch-granularity hint: each L2 miss
// pulls 256B instead of a 128B sector -> larger DRAM bursts on the random
// row gather (we consume the whole 2KB row, so nothing is wasted).
__device__ __forceinline__ int4 ldg_nc_256(const int4* p) {
    int4 v;
    asm volatile("ld.global.nc.L2::256B.v4.b32 {%0,%1,%2,%3}, [%4];"
                 : "=r"(v.x), "=r"(v.y), "=r"(v.z), "=r"(v.w)
                 : "l"(p));
    return v;
}

// One warp per 2 tokens. All 8 row loads (+2 scale loads) are issued before
// any consume -> ~10 independent loads in flight per thread-chain. Indices /
// scales are warp-broadcast. Dtype (int64 vs int32) detected inline via
// ballot over odd 32-bit words (int64 little-endian non-negative => all 0).
__global__ __launch_bounds__(WARPS_PER_BLOCK * 32)
void quant_embed_mlp_kernel(const unsigned int* __restrict__ x_raw,
                            const int4* __restrict__ w4,
                            const float* __restrict__ scales,
                            float4* __restrict__ out4,
                            int n_tokens)
{
    const int warp_id = threadIdx.x >> 5;
    const int lane    = threadIdx.x & 31;

    // ---- inline dtype detection (uniform result across grid) ----
    unsigned probe = 0u;
    {
        int wmax = n_tokens * 2;          // words available if int64
        int widx = 2 * lane + 1;
        if (widx < wmax) probe = x_raw[widx];
    }
    const bool is64 = (__ballot_sync(0xFFFFFFFFu, probe != 0u) == 0u);

    const int base_token = (blockIdx.x * WARPS_PER_BLOCK + warp_id) * TOK_PER_WARP;
    if (base_token >= n_tokens) return;
    const bool has1 = (base_token + 1) < n_tokens;

    // ---- indices (lane 0/1 load, broadcast) ----
    long long myidx = 0;
    if (lane < TOK_PER_WARP && base_token + lane < n_tokens) {
        myidx = is64 ? ((const long long*)x_raw)[base_token + lane]
                     : (long long)((const int*)x_raw)[base_token + lane];
    }
    const long long idx0 = __shfl_sync(0xFFFFFFFFu, myidx, 0);
    const long long idx1 = __shfl_sync(0xFFFFFFFFu, myidx, 1);

    const int4* r0 = w4 + idx0 * CHUNKS;
    const int4* r1 = w4 + idx1 * CHUNKS;

    // ---- issue ALL loads back-to-back (8 row loads + scales) ----
    int4 a0 = ldg_nc_256(&r0[lane]);
    int4 a1 = ldg_nc_256(&r0[lane + 32]);
    int4 a2 = ldg_nc_256(&r0[lane + 64]);
    int4 a3 = ldg_nc_256(&r0[lane + 96]);
    int4 b0, b1, b2, b3;
    if (has1) {
        b0 = ldg_nc_256(&r1[lane]);
        b1 = ldg_nc_256(&r1[lane + 32]);
        b2 = ldg_nc_256(&r1[lane + 64]);
        b3 = ldg_nc_256(&r1[lane + 96]);
    }
    const float s0 = __ldg(&scales[idx0]);
    const float s1 = has1 ? __ldg(&scales[idx1]) : 0.0f;

    // ---- dequant + streaming stores (don't pollute L2 with output) ----
    float4* o0 = out4 + (long long)base_token * CHUNKS;
    __stcs(&o0[lane],      make_float4((float)a0.x * s0, (float)a0.y * s0,
                                       (float)a0.z * s0, (float)a0.w * s0));
    __stcs(&o0[lane + 32], make_float4((float)a1.x * s0, (float)a1.y * s0,
                                       (float)a1.z * s0, (float)a1.w * s0));
    __stcs(&o0[lane + 64], make_float4((float)a2.x * s0, (float)a2.y * s0,
                                       (float)a2.z * s0, (float)a2.w * s0));
    __stcs(&o0[lane + 96], make_float4((float)a3.x * s0, (float)a3.y * s0,
                                       (float)a3.z * s0, (float)a3.w * s0));
    if (has1) {
        float4* o1 = out4 + (long long)(base_token + 1) * CHUNKS;
        __stcs(&o1[lane],      make_float4((float)b0.x * s1, (float)b0.y * s1,
                                           (float)b0.z * s1, (float)b0.w * s1));
        __stcs(&o1[lane + 32], make_float4((float)b1.x * s1, (float)b1.y * s1,
                                           (float)b1.z * s1, (float)b1.w * s1));
        __stcs(&o1[lane + 64], make_float4((float)b2.x * s1, (float)b2.y * s1,
                                           (float)b2.z * s1, (float)b2.w * s1));
        __stcs(&o1[lane + 96], make_float4((float)b3.x * s1, (float)b3.y * s1,
                                           (float)b3.z * s1, (float)b3.w * s1));
    }
}

// Generic fallback for dims other than 512.
__global__ __launch_bounds__(256)
void quant_embed_generic_kernel(const unsigned int* __restrict__ x_raw,
                                const int4* __restrict__ w4,
                                const float* __restrict__ scales,
                                float4* __restrict__ out4,
                                int chunks_per_row, int n_tokens)
{
    const int lane = threadIdx.x & 31;
    unsigned probe = 0u;
    {
        int wmax = n_tokens * 2;
        int widx = 2 * lane + 1;
        if (widx < wmax) probe = x_raw[widx];
    }
    const bool is64 = (__ballot_sync(0xFFFFFFFFu, probe != 0u) == 0u);

    const int warps_per_block = blockDim.x >> 5;
    const int token = blockIdx.x * warps_per_block + (threadIdx.x >> 5);
    if (token >= n_tokens) return;
    long long idx = is64 ? ((const long long*)x_raw)[token]
                         : (long long)((const int*)x_raw)[token];
    float s = __ldg(&scales[idx]);
    const int4* wrow = w4 + idx * chunks_per_row;
    float4* orow = out4 + (long long)token * chunks_per_row;
    for (int c = lane; c < chunks_per_row; c += 32) {
        int4 w = __ldg(&wrow[c]);
        __stcs(&orow[c], make_float4((float)w.x * s, (float)w.y * s,
                                     (float)w.z * s, (float)w.w * s));
    }
}

extern "C" void kernel_launch(void* const* d_in, const int* in_sizes, int n_in,
                              void* d_out, int out_size) {
    const unsigned int* x      = (const unsigned int*)d_in[0];
    const int4*         w4     = (const int4*)d_in[1];
    const float*        scales = (const float*)d_in[2];
    float4*             out4   = (float4*)d_out;

    const int n_tokens = in_sizes[0];
    const int dim      = out_size / n_tokens;   // 512
    const int chunks   = dim / 4;               // 128

    if (chunks == CHUNKS) {
        const int tokens_per_block = WARPS_PER_BLOCK * TOK_PER_WARP;  // 16
        const int blocks = (n_tokens + tokens_per_block - 1) / tokens_per_block;
        quant_embed_mlp_kernel<<<blocks, WARPS_PER_BLOCK * 32>>>(
            x, w4, scales, out4, n_tokens);
    } else {
        const int threads = 256;
        const int wpb = threads / 32;
        const int blocks = (n_tokens + wpb - 1) / wpb;
        quant_embed_generic_kernel<<<blocks, threads>>>(x, w4, scales, out4,
                                                        chunks, n_tokens);
    }
}